// round 6
// baseline (speedup 1.0000x reference)
#include <cuda_runtime.h>
#include <cuda_bf16.h>
#include <math.h>

// ---------------------------------------------------------------------------
// VQ-VAE vector quantizer, GB300 sm_103a
//   N=65536 tokens, D=256, K=1024 codes, fp32
//
// Reference-rounding-faithful distance:
//   dist_k = fp32( fp32(xnorm + cnorm_k) - 2*dot_k )
//   dot_k  = sequential fp32 FMA chain over d = 0..255 (ascending)
//   argmin = lowest index on exactly-equal rounded distances
// ---------------------------------------------------------------------------

#define NTOK 65536
#define DIM  256
#define KCB  1024

#define OFF_LOSS   16777216
#define OFF_IDX    16777217
#define OFF_PERP   16842753
#define OFF_NCS    16842754
#define OFF_EMAW   16843778
#define OFF_W      17105922

// scratch (device globals -- no allocation allowed)
__device__ float  g_cnorm[KCB];
__device__ float  g_xnorm[NTOK];
__device__ int    g_idx[NTOK];
__device__ float  g_counts[KCB];
__device__ float  g_dw[KCB * DIM];
__device__ double g_loss;
__device__ float  g_newcs[KCB];

// ---------------------------------------------------------------------------
// packed f32x2 helpers (Blackwell FFMA2 -- only reachable via PTX).
// Each lane is an independent IEEE RNE fp32 FMA -> chain is bit-identical to
// sequential scalar fmaf accumulation.
// ---------------------------------------------------------------------------
__device__ __forceinline__ unsigned long long dup_f32x2(float a) {
    unsigned long long r;
    asm("mov.b64 %0, {%1, %1};" : "=l"(r) : "f"(a));
    return r;
}
__device__ __forceinline__ unsigned long long fma_f32x2(unsigned long long a,
                                                        unsigned long long b,
                                                        unsigned long long c) {
    unsigned long long d;
    asm("fma.rn.f32x2 %0, %1, %2, %3;" : "=l"(d) : "l"(a), "l"(b), "l"(c));
    return d;
}
__device__ __forceinline__ float2 unpack_f32x2(unsigned long long v) {
    float2 r;
    asm("mov.b64 {%0, %1}, %2;" : "=f"(r.x), "=f"(r.y) : "l"(v));
    return r;
}

// ---------------------------------------------------------------------------
// 0) zero scratch
// ---------------------------------------------------------------------------
__global__ void zero_kernel() {
    int i = blockIdx.x * blockDim.x + threadIdx.x;
    int stride = gridDim.x * blockDim.x;
    for (int j = i; j < KCB * DIM; j += stride) g_dw[j] = 0.0f;
    if (i < KCB) g_counts[i] = 0.0f;
    if (i == 0)  g_loss = 0.0;
}

// ---------------------------------------------------------------------------
// 1) row squared-norms: one warp per row. Any accumulation order is fine:
//    cnorm is ~1e-4 (low bits can't move the ulp(256)~3e-5 bucket), and an
//    xnorm ulp error shifts all of a token's distances by the same exact
//    lattice amount (order- and tie-preserving).
// ---------------------------------------------------------------------------
__global__ void rownorm_kernel(const float* __restrict__ M,
                               float* __restrict__ out, int nrows) {
    int w    = (blockIdx.x * blockDim.x + threadIdx.x) >> 5;
    int lane = threadIdx.x & 31;
    if (w >= nrows) return;
    const float4* row = (const float4*)(M + (size_t)w * DIM);
    float s = 0.0f;
    float4 v = row[lane];
    s += v.x * v.x + v.y * v.y + v.z * v.z + v.w * v.w;
    v = row[32 + lane];
    s += v.x * v.x + v.y * v.y + v.z * v.z + v.w * v.w;
#pragma unroll
    for (int off = 16; off >= 1; off >>= 1)
        s += __shfl_xor_sync(0xffffffffu, s, off);
    if (lane == 0) out[w] = s;
}

// ---------------------------------------------------------------------------
// 2) fused GEMM + reference-rounded argmin
//    BM=128 tokens/block, BN=128 code chunk, BK=32, 256 threads, 8x8/thread.
//    dot accumulated sequentially over d ascending (single FMA chain).
// ---------------------------------------------------------------------------
#define BM 128
#define BN 128
#define BK 32
#define PAD 4

__global__ __launch_bounds__(256, 2)
void gemm_argmin_kernel(const float* __restrict__ X,
                        const float* __restrict__ C,
                        float* __restrict__ out_idx) {
    __shared__ __align__(16) float As[BK][BM + PAD];  // [d][token]
    __shared__ __align__(16) float Bs[BK][BN + PAD];  // [d][code]
    __shared__ float cn_sh[KCB];

    const int tid = threadIdx.x;
    const int tx  = tid & 15;       // code-group
    const int ty  = tid >> 4;       // token-group
    const int bm  = blockIdx.x * BM;

    // codebook norms into smem (read in epilogue)
    for (int i = tid; i < KCB; i += 256) cn_sh[i] = g_cnorm[i];

    // token norms for this thread's 8 rows
    float xnr[8];
#pragma unroll
    for (int r = 0; r < 8; r++) {
        int row = bm + ((r < 4) ? (ty * 4 + r) : (64 + ty * 4 + (r - 4)));
        xnr[r] = g_xnorm[row];
    }

    float bestS[8];
    int   bestI[8];
#pragma unroll
    for (int r = 0; r < 8; r++) { bestS[r] = 3.4e38f; bestI[r] = 0; }

    const int lr = tid >> 3;        // 0..31
    const int lc = (tid & 7) * 4;   // 0,4,...,28

    for (int cb0 = 0; cb0 < KCB; cb0 += BN) {
        unsigned long long acc[8][4];
#pragma unroll
        for (int r = 0; r < 8; r++)
#pragma unroll
            for (int j = 0; j < 4; j++) acc[r][j] = 0ULL;

        for (int d0 = 0; d0 < DIM; d0 += BK) {
            // load + transpose tiles into smem
#pragma unroll
            for (int i = 0; i < 4; i++) {
                float4 va = *(const float4*)(X + (size_t)(bm + lr + i * 32) * DIM + d0 + lc);
                As[lc + 0][lr + i * 32] = va.x;
                As[lc + 1][lr + i * 32] = va.y;
                As[lc + 2][lr + i * 32] = va.z;
                As[lc + 3][lr + i * 32] = va.w;
                float4 vb = *(const float4*)(C + (size_t)(cb0 + lr + i * 32) * DIM + d0 + lc);
                Bs[lc + 0][lr + i * 32] = vb.x;
                Bs[lc + 1][lr + i * 32] = vb.y;
                Bs[lc + 2][lr + i * 32] = vb.z;
                Bs[lc + 3][lr + i * 32] = vb.w;
            }
            __syncthreads();

#pragma unroll 4
            for (int k = 0; k < BK; k++) {
                float4 a0 = *(const float4*)&As[k][ty * 4];
                float4 a1 = *(const float4*)&As[k][64 + ty * 4];
                ulonglong2 b0 = *(const ulonglong2*)&Bs[k][tx * 4];
                ulonglong2 b1 = *(const ulonglong2*)&Bs[k][64 + tx * 4];

                unsigned long long a2;
                a2 = dup_f32x2(a0.x);
                acc[0][0] = fma_f32x2(a2, b0.x, acc[0][0]);
                acc[0][1] = fma_f32x2(a2, b0.y, acc[0][1]);
                acc[0][2] = fma_f32x2(a2, b1.x, acc[0][2]);
                acc[0][3] = fma_f32x2(a2, b1.y, acc[0][3]);
                a2 = dup_f32x2(a0.y);
                acc[1][0] = fma_f32x2(a2, b0.x, acc[1][0]);
                acc[1][1] = fma_f32x2(a2, b0.y, acc[1][1]);
                acc[1][2] = fma_f32x2(a2, b1.x, acc[1][2]);
                acc[1][3] = fma_f32x2(a2, b1.y, acc[1][3]);
                a2 = dup_f32x2(a0.z);
                acc[2][0] = fma_f32x2(a2, b0.x, acc[2][0]);
                acc[2][1] = fma_f32x2(a2, b0.y, acc[2][1]);
                acc[2][2] = fma_f32x2(a2, b1.x, acc[2][2]);
                acc[2][3] = fma_f32x2(a2, b1.y, acc[2][3]);
                a2 = dup_f32x2(a0.w);
                acc[3][0] = fma_f32x2(a2, b0.x, acc[3][0]);
                acc[3][1] = fma_f32x2(a2, b0.y, acc[3][1]);
                acc[3][2] = fma_f32x2(a2, b1.x, acc[3][2]);
                acc[3][3] = fma_f32x2(a2, b1.y, acc[3][3]);
                a2 = dup_f32x2(a1.x);
                acc[4][0] = fma_f32x2(a2, b0.x, acc[4][0]);
                acc[4][1] = fma_f32x2(a2, b0.y, acc[4][1]);
                acc[4][2] = fma_f32x2(a2, b1.x, acc[4][2]);
                acc[4][3] = fma_f32x2(a2, b1.y, acc[4][3]);
                a2 = dup_f32x2(a1.y);
                acc[5][0] = fma_f32x2(a2, b0.x, acc[5][0]);
                acc[5][1] = fma_f32x2(a2, b0.y, acc[5][1]);
                acc[5][2] = fma_f32x2(a2, b1.x, acc[5][2]);
                acc[5][3] = fma_f32x2(a2, b1.y, acc[5][3]);
                a2 = dup_f32x2(a1.z);
                acc[6][0] = fma_f32x2(a2, b0.x, acc[6][0]);
                acc[6][1] = fma_f32x2(a2, b0.y, acc[6][1]);
                acc[6][2] = fma_f32x2(a2, b1.x, acc[6][2]);
                acc[6][3] = fma_f32x2(a2, b1.y, acc[6][3]);
                a2 = dup_f32x2(a1.w);
                acc[7][0] = fma_f32x2(a2, b0.x, acc[7][0]);
                acc[7][1] = fma_f32x2(a2, b0.y, acc[7][1]);
                acc[7][2] = fma_f32x2(a2, b1.x, acc[7][2]);
                acc[7][3] = fma_f32x2(a2, b1.y, acc[7][3]);
            }
            __syncthreads();
        }

        // reference-faithful epilogue: dist = fp32(fp32(xn + cn) - 2*dot),
        // scanning columns in ascending index order (lowest-index tie-break)
#pragma unroll
        for (int r = 0; r < 8; r++) {
#pragma unroll
            for (int j = 0; j < 4; j++) {
                float2 v = unpack_f32x2(acc[r][j]);
                int c0 = cb0 + ((j < 2) ? (tx * 4 + 2 * j) : (64 + tx * 4 + 2 * (j - 2)));
                float t0 = xnr[r] + cn_sh[c0];       // fp32 RNE add (ref order)
                float t1 = xnr[r] + cn_sh[c0 + 1];
                float s0 = t0 - 2.0f * v.x;          // 2*dot exact; one RNE sub
                float s1 = t1 - 2.0f * v.y;
                if (s0 < bestS[r]) { bestS[r] = s0; bestI[r] = c0; }
                if (s1 < bestS[r]) { bestS[r] = s1; bestI[r] = c0 + 1; }
            }
        }
    }

    // reduce argmin across the 16 tx-lanes sharing each token row
#pragma unroll
    for (int r = 0; r < 8; r++) {
        float s = bestS[r];
        int   i = bestI[r];
#pragma unroll
        for (int off = 8; off >= 1; off >>= 1) {
            float os = __shfl_xor_sync(0xffffffffu, s, off);
            int   oi = __shfl_xor_sync(0xffffffffu, i, off);
            if (os < s || (os == s && oi < i)) { s = os; i = oi; }
        }
        if (tx == 0) {
            int row = bm + ((r < 4) ? (ty * 4 + r) : (64 + ty * 4 + (r - 4)));
            g_idx[row]   = i;
            out_idx[row] = (float)i;
        }
    }
}

// ---------------------------------------------------------------------------
// 3) gather/quantize + loss + EMA histogram. one warp per token.
//    quantized_st = x + (c - x) elementwise (matches reference rounding).
// ---------------------------------------------------------------------------
__global__ void assign_kernel(const float* __restrict__ X,
                              const float* __restrict__ C,
                              float* __restrict__ outQ) {
    int n    = (blockIdx.x * blockDim.x + threadIdx.x) >> 5;
    int lane = threadIdx.x & 31;
    int idx  = g_idx[n];

    const float4* xr = (const float4*)(X + (size_t)n * DIM);
    const float4* cr = (const float4*)(C + (size_t)idx * DIM);
    float4*       qr = (float4*)(outQ + (size_t)n * DIM);
    float* dwrow = &g_dw[(size_t)idx * DIM];

    float local = 0.0f;
#pragma unroll
    for (int h = 0; h < 2; h++) {
        int e = lane + h * 32;
        float4 xv = xr[e];
        float4 cv = cr[e];
        float4 qv;
        float d;
        d = cv.x - xv.x; qv.x = xv.x + d; local += d * d;
        d = cv.y - xv.y; qv.y = xv.y + d; local += d * d;
        d = cv.z - xv.z; qv.z = xv.z + d; local += d * d;
        d = cv.w - xv.w; qv.w = xv.w + d; local += d * d;
        qr[e] = qv;
        int db = e * 4;
        atomicAdd(&dwrow[db + 0], xv.x);
        atomicAdd(&dwrow[db + 1], xv.y);
        atomicAdd(&dwrow[db + 2], xv.z);
        atomicAdd(&dwrow[db + 3], xv.w);
    }
    if (lane == 0) atomicAdd(&g_counts[idx], 1.0f);

#pragma unroll
    for (int off = 16; off >= 1; off >>= 1)
        local += __shfl_xor_sync(0xffffffffu, local, off);
    if (lane == 0) atomicAdd(&g_loss, (double)local);
}

// ---------------------------------------------------------------------------
// 4) stats: new_cs (laplace-smoothed), perplexity, vq_loss. 1 block x 1024.
// ---------------------------------------------------------------------------
__global__ void stats_kernel(const float* __restrict__ ema_cs,
                             float* __restrict__ out_loss,
                             float* __restrict__ out_perp,
                             float* __restrict__ out_newcs) {
    __shared__ float sh[KCB];
    int k = threadIdx.x;

    float cnt = g_counts[k];
    float cs  = 0.99f * ema_cs[k] + 0.01f * cnt;

    sh[k] = cs;
    __syncthreads();
    for (int s = 512; s > 0; s >>= 1) {
        if (k < s) sh[k] += sh[k + s];
        __syncthreads();
    }
    float n_total = sh[0];
    __syncthreads();

    float ncs = (cs + 1e-5f) / (n_total + 0.01024f) * n_total;
    out_newcs[k] = ncs;
    g_newcs[k]   = ncs;

    float p = cnt * (1.0f / 65536.0f);
    sh[k] = p * logf(p + 1e-10f);
    __syncthreads();
    for (int s = 512; s > 0; s >>= 1) {
        if (k < s) sh[k] += sh[k + s];
        __syncthreads();
    }
    if (k == 0) {
        out_perp[0] = expf(-sh[0]);
        out_loss[0] = (float)(0.25 * g_loss / 16777216.0);
    }
}

// ---------------------------------------------------------------------------
// 5) new_ema_w, new_weight
// ---------------------------------------------------------------------------
__global__ void weights_kernel(const float* __restrict__ emaW,
                               float* __restrict__ outEmaW,
                               float* __restrict__ outW) {
    int i = blockIdx.x * blockDim.x + threadIdx.x;   // 0 .. K*D-1
    float w = 0.99f * emaW[i] + 0.01f * g_dw[i];
    outEmaW[i] = w;
    outW[i]    = w / g_newcs[i >> 8];
}

// ---------------------------------------------------------------------------
extern "C" void kernel_launch(void* const* d_in, const int* in_sizes, int n_in,
                              void* d_out, int out_size) {
    const float* X      = (const float*)d_in[0];   // inputs [N, D]
    const float* CB     = (const float*)d_in[1];   // codebook [K, D]
    const float* EMA_CS = (const float*)d_in[2];   // [K]
    const float* EMA_W  = (const float*)d_in[3];   // [K, D]
    float* out = (float*)d_out;

    float* out_q     = out;
    float* out_loss  = out + OFF_LOSS;
    float* out_idx   = out + OFF_IDX;
    float* out_perp  = out + OFF_PERP;
    float* out_ncs   = out + OFF_NCS;
    float* out_emaw  = out + OFF_EMAW;
    float* out_w     = out + OFF_W;

    float* g_cnorm_p;  cudaGetSymbolAddress((void**)&g_cnorm_p, g_cnorm);
    float* g_xnorm_p;  cudaGetSymbolAddress((void**)&g_xnorm_p, g_xnorm);

    zero_kernel<<<256, 256>>>();
    rownorm_kernel<<<KCB * 32 / 256, 256>>>(CB, g_cnorm_p, KCB);
    rownorm_kernel<<<NTOK * 32 / 256, 256>>>(X, g_xnorm_p, NTOK);
    gemm_argmin_kernel<<<NTOK / BM, 256>>>(X, CB, out_idx);
    assign_kernel<<<NTOK / 8, 256>>>(X, CB, out_q);
    stats_kernel<<<1, 1024>>>(EMA_CS, out_loss, out_perp, out_ncs);
    weights_kernel<<<KCB * DIM / 1024, 1024>>>(EMA_W, out_emaw, out_w);
}

// round 7
// speedup vs baseline: 1.3537x; 1.3537x over previous
#include <cuda_runtime.h>
#include <cuda_bf16.h>
#include <math.h>

// ---------------------------------------------------------------------------
// VQ-VAE vector quantizer, GB300 sm_103a
//   N=65536 tokens, D=256, K=1024 codes, fp32
//
// Reference-rounding-faithful distance:
//   dist_k = fp32( fp32(xnorm + cnorm_k) - 2*dot_k )
//   dot_k  = sequential fp32 FMA chain over d = 0..255 ascending
//   argmin = lowest index on exactly-equal rounded distances
//
// GEMM v3: X^T tile resident in smem (staged once, XOR-swizzled, conflict-
// free), C tiles double-buffered LDG->reg->STS, split-K halves for wave
// balance (1024 blocks, 1 CTA/SM), halves merged in assign_kernel with the
// same rounded-compare + lower-index-tie predicate.
// ---------------------------------------------------------------------------

#define NTOK 65536
#define DIM  256
#define KCB  1024

#define OFF_LOSS   16777216
#define OFF_IDX    16777217
#define OFF_PERP   16842753
#define OFF_NCS    16842754
#define OFF_EMAW   16843778
#define OFF_W      17105922

// scratch (device globals -- no allocation allowed)
__device__ float  g_cnorm[KCB];
__device__ float  g_xnorm[NTOK];
__device__ float  g_counts[KCB];
__device__ float  g_dw[KCB * DIM];
__device__ double g_loss;
__device__ float  g_newcs[KCB];
__device__ float  g_hdist[2 * NTOK];   // per-half best rounded distance
__device__ int    g_hidx[2 * NTOK];    // per-half best (global) index

// ---------------------------------------------------------------------------
// packed f32x2 helpers (Blackwell FFMA2 -- only reachable via PTX).
// Each lane is an independent IEEE RNE fp32 FMA -> chain is bit-identical to
// sequential scalar fmaf accumulation.
// ---------------------------------------------------------------------------
__device__ __forceinline__ unsigned long long dup_f32x2(float a) {
    unsigned long long r;
    asm("mov.b64 %0, {%1, %1};" : "=l"(r) : "f"(a));
    return r;
}
__device__ __forceinline__ unsigned long long fma_f32x2(unsigned long long a,
                                                        unsigned long long b,
                                                        unsigned long long c) {
    unsigned long long d;
    asm("fma.rn.f32x2 %0, %1, %2, %3;" : "=l"(d) : "l"(a), "l"(b), "l"(c));
    return d;
}
__device__ __forceinline__ float2 unpack_f32x2(unsigned long long v) {
    float2 r;
    asm("mov.b64 {%0, %1}, %2;" : "=f"(r.x), "=f"(r.y) : "l"(v));
    return r;
}

// XOR-swizzled [k][col] layout, row stride exactly 128 floats.
// 16B granule g = col>>2 gets low-3-bits XORed with (k>>2)&7:
//   - transposed STS (8 k-rows x fixed granule) -> 8 distinct bank groups
//   - float4 LDS (fixed k, granule ty / 16+ty)  -> conflict-free
__device__ __forceinline__ int sw_base(int k, int col) {
    int g  = col >> 2;
    int gs = (g & ~7) | ((g ^ (k >> 2)) & 7);
    return k * 128 + gs * 4 + (col & 3);
}

// ---------------------------------------------------------------------------
// 0) zero scratch
// ---------------------------------------------------------------------------
__global__ void zero_kernel() {
    int i = blockIdx.x * blockDim.x + threadIdx.x;
    int stride = gridDim.x * blockDim.x;
    for (int j = i; j < KCB * DIM; j += stride) g_dw[j] = 0.0f;
    if (i < KCB) g_counts[i] = 0.0f;
    if (i == 0)  g_loss = 0.0;
}

// ---------------------------------------------------------------------------
// 1) row squared-norms: one warp per row. (xnorm ulp jitter shifts a token's
//    whole distance row by the same lattice amount: order/tie preserving.)
// ---------------------------------------------------------------------------
__global__ void rownorm_kernel(const float* __restrict__ M,
                               float* __restrict__ out, int nrows) {
    int w    = (blockIdx.x * blockDim.x + threadIdx.x) >> 5;
    int lane = threadIdx.x & 31;
    if (w >= nrows) return;
    const float4* row = (const float4*)(M + (size_t)w * DIM);
    float s = 0.0f;
    float4 v = row[lane];
    s += v.x * v.x + v.y * v.y + v.z * v.z + v.w * v.w;
    v = row[32 + lane];
    s += v.x * v.x + v.y * v.y + v.z * v.z + v.w * v.w;
#pragma unroll
    for (int off = 16; off >= 1; off >>= 1)
        s += __shfl_xor_sync(0xffffffffu, s, off);
    if (lane == 0) out[w] = s;
}

// ---------------------------------------------------------------------------
// 2) fused GEMM + reference-rounded argmin (split-K halves)
//    block = 128 tokens x 512 codes (half), 256 threads, thread tile 8x8.
//    smem: As[256][128] resident X^T + Bs[2][32][128] C double-buffer + cn.
// ---------------------------------------------------------------------------
#define SM_BS 32768
#define SM_CN 40960
#define SMEM_BYTES (41472 * 4)

__global__ __launch_bounds__(256, 1)
void gemm_argmin_kernel(const float* __restrict__ X,
                        const float* __restrict__ C) {
    extern __shared__ float sm[];
    float* As = sm;             // [256][128] swizzled (resident X^T tile)
    float* Bs = sm + SM_BS;     // [2][32][128] swizzled (C tiles)
    float* cn = sm + SM_CN;     // [512] codebook norms for this half

    const int tid   = threadIdx.x;
    const int tx    = tid & 15;
    const int ty    = tid >> 4;
    const int tile  = blockIdx.x >> 1;
    const int half  = blockIdx.x & 1;
    const int bm    = tile * 128;
    const int kbase = half * 512;

    const int lr = tid >> 3;        // 0..31
    const int lc = (tid & 7) * 4;   // 0,4,...,28

    for (int i = tid; i < 512; i += 256) cn[i] = g_cnorm[kbase + i];

    // stage resident X^T tile once (conflict-free swizzled stores)
#pragma unroll
    for (int i = 0; i < 4; i++) {
        int tok = lr + i * 32;
        const float* xr = X + (size_t)(bm + tok) * DIM;
#pragma unroll
        for (int dd = 0; dd < 8; dd++) {
            float4 v = *(const float4*)(xr + dd * 32 + lc);
            int base = sw_base(dd * 32 + lc, tok);
            As[base]       = v.x;
            As[base + 128] = v.y;
            As[base + 256] = v.z;
            As[base + 384] = v.w;
        }
    }

    float xnr[8];
#pragma unroll
    for (int r = 0; r < 8; r++) {
        int row = bm + ((r < 4) ? (ty * 4 + r) : (64 + ty * 4 + (r - 4)));
        xnr[r] = g_xnorm[row];
    }

    float bestS[8];
    int   bestI[8];
#pragma unroll
    for (int r = 0; r < 8; r++) { bestS[r] = 3.4e38f; bestI[r] = 0; }

    for (int cb = 0; cb < 4; cb++) {
        const float* Cbase = C + (size_t)(kbase + cb * 128) * DIM;
        float4 cv[4];
        // prefetch + store stage 0
#pragma unroll
        for (int i = 0; i < 4; i++)
            cv[i] = *(const float4*)(Cbase + (size_t)(lr + i * 32) * DIM + lc);
#pragma unroll
        for (int i = 0; i < 4; i++) {
            int base = sw_base(lc, lr + i * 32);
            Bs[base]       = cv[i].x;
            Bs[base + 128] = cv[i].y;
            Bs[base + 256] = cv[i].z;
            Bs[base + 384] = cv[i].w;
        }
        __syncthreads();

        unsigned long long acc[8][4];
#pragma unroll
        for (int r = 0; r < 8; r++)
#pragma unroll
            for (int j = 0; j < 4; j++) acc[r][j] = 0ULL;

        for (int d0 = 0; d0 < 8; d0++) {
            // prefetch next C tile into regs (latency hidden by compute)
            if (d0 < 7) {
#pragma unroll
                for (int i = 0; i < 4; i++)
                    cv[i] = *(const float4*)(Cbase + (size_t)(lr + i * 32) * DIM
                                             + (d0 + 1) * 32 + lc);
            }
            const float* Arow = As + d0 * 32 * 128;
            const float* Brow = Bs + (d0 & 1) * 4096;

#pragma unroll
            for (int kk = 0; kk < 8; kk++) {
                const int tyg = ((ty & 8) | ((ty ^ kk) & 7)) * 4;
                const int txg = ((tx & 8) | ((tx ^ kk) & 7)) * 4;
#pragma unroll
                for (int m = 0; m < 4; m++) {
                    const float* Ar = Arow + (kk * 4 + m) * 128;
                    const float* Br = Brow + (kk * 4 + m) * 128;
                    float4 a0 = *(const float4*)(Ar + tyg);
                    float4 a1 = *(const float4*)(Ar + 64 + tyg);
                    ulonglong2 b0 = *(const ulonglong2*)(Br + txg);
                    ulonglong2 b1 = *(const ulonglong2*)(Br + 64 + txg);
                    float av[8] = {a0.x, a0.y, a0.z, a0.w,
                                   a1.x, a1.y, a1.z, a1.w};
                    unsigned long long bv[4] = {b0.x, b0.y, b1.x, b1.y};
#pragma unroll
                    for (int r = 0; r < 8; r++) {
                        unsigned long long ad = dup_f32x2(av[r]);
#pragma unroll
                        for (int j = 0; j < 4; j++)
                            acc[r][j] = fma_f32x2(ad, bv[j], acc[r][j]);
                    }
                }
            }

            if (d0 < 7) {
                const int nb = ((d0 + 1) & 1) * 4096;
#pragma unroll
                for (int i = 0; i < 4; i++) {
                    int base = nb + sw_base(lc, lr + i * 32);
                    Bs[base]       = cv[i].x;
                    Bs[base + 128] = cv[i].y;
                    Bs[base + 256] = cv[i].z;
                    Bs[base + 384] = cv[i].w;
                }
                __syncthreads();
            }
        }

        // reference-faithful epilogue: dist = fp32(fp32(xn + cn) - 2*dot),
        // columns ascending (lowest-index tie-break)
#pragma unroll
        for (int r = 0; r < 8; r++) {
#pragma unroll
            for (int j = 0; j < 4; j++) {
                float2 v = unpack_f32x2(acc[r][j]);
                int cl = cb * 128 +
                         ((j < 2) ? (tx * 4 + 2 * j) : (64 + tx * 4 + 2 * (j - 2)));
                float t0 = xnr[r] + cn[cl];
                float t1 = xnr[r] + cn[cl + 1];
                float s0 = t0 - 2.0f * v.x;
                float s1 = t1 - 2.0f * v.y;
                if (s0 < bestS[r]) { bestS[r] = s0; bestI[r] = cl; }
                if (s1 < bestS[r]) { bestS[r] = s1; bestI[r] = cl + 1; }
            }
        }
        // no barrier needed: next cb writes Bs[0]; last reads of Bs[0] were
        // barriered at the d0=6 -> 7 transition; Bs[1] readers don't collide.
    }

    // reduce argmin across the 16 tx-lanes sharing each token row
#pragma unroll
    for (int r = 0; r < 8; r++) {
        float s = bestS[r];
        int   i = bestI[r];
#pragma unroll
        for (int off = 8; off >= 1; off >>= 1) {
            float os = __shfl_xor_sync(0xffffffffu, s, off);
            int   oi = __shfl_xor_sync(0xffffffffu, i, off);
            if (os < s || (os == s && oi < i)) { s = os; i = oi; }
        }
        if (tx == 0) {
            int row = bm + ((r < 4) ? (ty * 4 + r) : (64 + ty * 4 + (r - 4)));
            g_hdist[half * NTOK + row] = s;
            g_hidx[half * NTOK + row]  = kbase + i;
        }
    }
}

// ---------------------------------------------------------------------------
// 3) merge halves + gather/quantize + loss + EMA histogram. one warp/token.
//    merge predicate == full ascending scan: strictly-less wins, tie -> the
//    lower-index half (half 0 indices < half 1 indices always).
// ---------------------------------------------------------------------------
__global__ void assign_kernel(const float* __restrict__ X,
                              const float* __restrict__ C,
                              float* __restrict__ outQ,
                              float* __restrict__ out_idx) {
    int n    = (blockIdx.x * blockDim.x + threadIdx.x) >> 5;
    int lane = threadIdx.x & 31;

    float h0 = g_hdist[n];
    float h1 = g_hdist[NTOK + n];
    int   i0 = g_hidx[n];
    int   i1 = g_hidx[NTOK + n];
    int   idx = (h1 < h0) ? i1 : i0;
    if (lane == 0) out_idx[n] = (float)idx;

    const float4* xr = (const float4*)(X + (size_t)n * DIM);
    const float4* cr = (const float4*)(C + (size_t)idx * DIM);
    float4*       qr = (float4*)(outQ + (size_t)n * DIM);
    float* dwrow = &g_dw[(size_t)idx * DIM];

    float local = 0.0f;
#pragma unroll
    for (int h = 0; h < 2; h++) {
        int e = lane + h * 32;
        float4 xv = xr[e];
        float4 cv = cr[e];
        float4 qv;
        float d;
        d = cv.x - xv.x; qv.x = xv.x + d; local += d * d;
        d = cv.y - xv.y; qv.y = xv.y + d; local += d * d;
        d = cv.z - xv.z; qv.z = xv.z + d; local += d * d;
        d = cv.w - xv.w; qv.w = xv.w + d; local += d * d;
        qr[e] = qv;
        int db = e * 4;
        atomicAdd(&dwrow[db + 0], xv.x);
        atomicAdd(&dwrow[db + 1], xv.y);
        atomicAdd(&dwrow[db + 2], xv.z);
        atomicAdd(&dwrow[db + 3], xv.w);
    }
    if (lane == 0) atomicAdd(&g_counts[idx], 1.0f);

#pragma unroll
    for (int off = 16; off >= 1; off >>= 1)
        local += __shfl_xor_sync(0xffffffffu, local, off);
    if (lane == 0) atomicAdd(&g_loss, (double)local);
}

// ---------------------------------------------------------------------------
// 4) stats: new_cs (laplace-smoothed), perplexity, vq_loss. 1 block x 1024.
// ---------------------------------------------------------------------------
__global__ void stats_kernel(const float* __restrict__ ema_cs,
                             float* __restrict__ out_loss,
                             float* __restrict__ out_perp,
                             float* __restrict__ out_newcs) {
    __shared__ float sh[KCB];
    int k = threadIdx.x;

    float cnt = g_counts[k];
    float cs  = 0.99f * ema_cs[k] + 0.01f * cnt;

    sh[k] = cs;
    __syncthreads();
    for (int s = 512; s > 0; s >>= 1) {
        if (k < s) sh[k] += sh[k + s];
        __syncthreads();
    }
    float n_total = sh[0];
    __syncthreads();

    float ncs = (cs + 1e-5f) / (n_total + 0.01024f) * n_total;
    out_newcs[k] = ncs;
    g_newcs[k]   = ncs;

    float p = cnt * (1.0f / 65536.0f);
    sh[k] = p * logf(p + 1e-10f);
    __syncthreads();
    for (int s = 512; s > 0; s >>= 1) {
        if (k < s) sh[k] += sh[k + s];
        __syncthreads();
    }
    if (k == 0) {
        out_perp[0] = expf(-sh[0]);
        out_loss[0] = (float)(0.25 * g_loss / 16777216.0);
    }
}

// ---------------------------------------------------------------------------
// 5) new_ema_w, new_weight
// ---------------------------------------------------------------------------
__global__ void weights_kernel(const float* __restrict__ emaW,
                               float* __restrict__ outEmaW,
                               float* __restrict__ outW) {
    int i = blockIdx.x * blockDim.x + threadIdx.x;   // 0 .. K*D-1
    float w = 0.99f * emaW[i] + 0.01f * g_dw[i];
    outEmaW[i] = w;
    outW[i]    = w / g_newcs[i >> 8];
}

// ---------------------------------------------------------------------------
extern "C" void kernel_launch(void* const* d_in, const int* in_sizes, int n_in,
                              void* d_out, int out_size) {
    const float* X      = (const float*)d_in[0];   // inputs [N, D]
    const float* CB     = (const float*)d_in[1];   // codebook [K, D]
    const float* EMA_CS = (const float*)d_in[2];   // [K]
    const float* EMA_W  = (const float*)d_in[3];   // [K, D]
    float* out = (float*)d_out;

    float* out_q     = out;
    float* out_loss  = out + OFF_LOSS;
    float* out_idx   = out + OFF_IDX;
    float* out_perp  = out + OFF_PERP;
    float* out_ncs   = out + OFF_NCS;
    float* out_emaw  = out + OFF_EMAW;
    float* out_w     = out + OFF_W;

    float* g_cnorm_p;  cudaGetSymbolAddress((void**)&g_cnorm_p, g_cnorm);
    float* g_xnorm_p;  cudaGetSymbolAddress((void**)&g_xnorm_p, g_xnorm);

    cudaFuncSetAttribute(gemm_argmin_kernel,
                         cudaFuncAttributeMaxDynamicSharedMemorySize,
                         SMEM_BYTES);

    zero_kernel<<<256, 256>>>();
    rownorm_kernel<<<KCB * 32 / 256, 256>>>(CB, g_cnorm_p, KCB);
    rownorm_kernel<<<NTOK * 32 / 256, 256>>>(X, g_xnorm_p, NTOK);
    gemm_argmin_kernel<<<1024, 256, SMEM_BYTES>>>(X, CB);
    assign_kernel<<<NTOK / 8, 256>>>(X, CB, out_q, out_idx);
    stats_kernel<<<1, 1024>>>(EMA_CS, out_loss, out_perp, out_ncs);
    weights_kernel<<<KCB * DIM / 1024, 1024>>>(EMA_W, out_emaw, out_w);
}